// round 9
// baseline (speedup 1.0000x reference)
#include <cuda_runtime.h>

// Problem constants: H=64, M=N=128, k=9, w=3
#define PTOT (64 * 128 * 128)
#define KNN  9

// Tile: 16 x 4 x 4 voxels per block; halo 18 x 6 x 6
#define TX 16
#define TY 4
#define TZ 4
#define HX 18
#define HY 6
#define HROWS (HX * HY * 6)     // 648
#define HXY (HX * HY)           // 108

// Scratch: per-voxel 9 selected values (12-float padded row, as 3 float4)
// and 9 window codes (bytes packed in 3 u32 words).
__device__ float4       g_val4[PTOT * 3];    // 50.3 MB
__device__ unsigned int g_code32[PTOT * 3];  // 12.6 MB

// No-op kernels: shift ncu's fixed -s 5 capture onto pass1 (4 launches/call
// -> launch idx 5 == position 1 == pass1). ~1us each.
__global__ void dummyA_kernel() {}
__global__ void dummyB_kernel() {}

// ---------------------------------------------------------------------------
// Pass 1 (unchanged — measured ~72us): stable top-9 of 27 periodic window
// neighbors by |v - center|.
//   rank(c) = #{j<c: d_j <= d_c} + #{j>c: d_j < d_c}
// One compare per unordered pair, split between FSETP (FMA pipe) and
// ISETP-on-abs-bits (ALU pipe; identical order for d >= 0), with the center
// candidate (13, d=0) algebraically folded into the counter init.
// ---------------------------------------------------------------------------
__global__ __launch_bounds__(256) void pass1_kernel(const float* __restrict__ anat) {
    __shared__ float        s_anat[HROWS];
    __shared__ float4       s_val[256 * 3];
    __shared__ unsigned int s_code[256 * 3];

    int tid = threadIdx.x;
    int lx = tid & 15, ly = (tid >> 4) & 3, lz = tid >> 6;
    int x0 = blockIdx.x * TX, y0 = blockIdx.y * TY, z0 = blockIdx.z * TZ;

    for (int t = tid; t < HROWS; t += 256) {
        int hx = t % HX; int r = t / HX; int hy = r % HY; int hz = r / HY;
        int gx = (x0 + hx + 127) & 127;
        int gy = (y0 + hy + 127) & 127;
        int gz = (z0 + hz + 63) & 63;
        s_anat[t] = __ldg(&anat[(gz << 14) | (gy << 7) | gx]);
    }
    __syncthreads();

    int center = (lz + 1) * HXY + (ly + 1) * HX + (lx + 1);
    float ac = s_anat[center];

    float fd[27];
#pragma unroll
    for (int oz = 0; oz < 3; ++oz)
#pragma unroll
        for (int oy = 0; oy < 3; ++oy)
#pragma unroll
            for (int ox = 0; ox < 3; ++ox) {
                int c = oz * 9 + oy * 3 + ox;
                fd[c] = fabsf(s_anat[center + (oz - 1) * HXY + (oy - 1) * HX + (ox - 1)] - ac);
            }

    // Counter init encodes rank_c += 1 for all c > 13 (pairs with center).
    unsigned ri[7] = { 0u, 0u, 0u, 0x01010000u, 0x01010101u, 0x01010101u, 0x00010101u };
    float    rf[14];
#pragma unroll
    for (int k = 0; k < 14; ++k) rf[k] = 0.0f;

    // Pairs (j<13, c=13): d_j == 0 ?
#pragma unroll
    for (int j = 0; j < 13; ++j) {
        if (__float_as_uint(fd[j]) == 0u)
            ri[3] += (1u << 8);                 // rank_13 byte slot
        else
            ri[j >> 2] += (1u << ((j & 3) * 8));
    }

    // All remaining pairs (both endpoints != 13), diagonal order.
#pragma unroll
    for (int o = 1; o < 27; ++o)
#pragma unroll
        for (int j = 0; j + o < 27; ++j) {
            const int c = j + o;
            if (j == 13 || c == 13) continue;
            if (j & 1) {
                if (__float_as_uint(fd[j]) <= __float_as_uint(fd[c]))
                    ri[c >> 2] += (1u << ((c & 3) * 8));
                else
                    ri[j >> 2] += (1u << ((j & 3) * 8));
            } else {
                if (fd[j] <= fd[c])
                    rf[c >> 1] += ((c & 1) ? 1024.0f : 1.0f);
                else
                    rf[j >> 1] += ((j & 1) ? 1024.0f : 1.0f);
            }
        }

    int fi[14];
#pragma unroll
    for (int k = 0; k < 14; ++k) fi[k] = (int)rf[k];

    float*         svf = (float*)s_val;
    unsigned char* scb = (unsigned char*)s_code;
#pragma unroll
    for (int c = 0; c < 27; ++c) {
        int r = (int)((ri[c >> 2] >> ((c & 3) * 8)) & 255u)
              + ((c & 1) ? (fi[c >> 1] >> 10) : (fi[c >> 1] & 1023));
        if (r < KNN) {
            int oz = c / 9, rem = c - 9 * oz, oy = rem / 3, ox = rem - 3 * oy; // compile-time
            svf[tid * 12 + r] = s_anat[center + (oz - 1) * HXY + (oy - 1) * HX + (ox - 1)];
            scb[tid * 12 + r] = (unsigned char)c;
        }
    }
    __syncthreads();

    // Coalesced copy-out: 16 (lz,ly) lines x 48 float4 per line.
    for (int q = tid; q < 768; q += 256) {
        int line = q / 48, off = q - line * 48;
        int llz = line >> 2, lly = line & 3;
        int vox = ((z0 + llz) << 14) | ((y0 + lly) << 7) | x0;
        g_val4[vox * 3 + off]   = s_val[q];
        g_code32[vox * 3 + off] = s_code[q];
    }
}

// ---------------------------------------------------------------------------
// Pass 2 (R7 structure): halo of 648 g_val rows staged in smem at scalar
// stride 9 (gcd(9,32)=1 -> divergent row reads near conflict-free).
// CHANGE vs R7: halo loaded FLAT (consecutive thread <-> consecutive float4,
// ~4-6 sectors per warp-instr, each sector touched once) instead of 3
// strided LDG.128 per row (12 sectors/instr, 3x re-touch).
// Output staged through the same buffer, written back as float4.
// ---------------------------------------------------------------------------
__global__ __launch_bounds__(256) void pass2_kernel(const float* __restrict__ ksig,
                                                    float* __restrict__ out) {
    __shared__ __align__(16) float s9[HROWS * 9];   // 23328 B, reused for out staging
    __shared__ int s_tab[27];

    int tid = threadIdx.x;
    int lx = tid & 15, ly = (tid >> 4) & 3, lz = tid >> 6;
    int x0 = blockIdx.x * TX, y0 = blockIdx.y * TY, z0 = blockIdx.z * TZ;

    if (tid < 27) {
        int oz = tid / 9, rem = tid - 9 * oz, oy = rem / 3, ox = rem - 3 * oy;
        s_tab[tid] = (oz - 1) * HXY + (oy - 1) * HX + (ox - 1);
    }

    // Flat coalesced halo load: 1944 float4s, scatter to stride-9 scalar rows.
    for (int t = tid; t < HROWS * 3; t += 256) {
        int row = t / 3, k = t - row * 3;
        int hx = row % HX; int r = row / HX; int hy = r % HY; int hz = r / HY;
        int gx = (x0 + hx + 127) & 127;
        int gy = (y0 + hy + 127) & 127;
        int gz = (z0 + hz + 63) & 63;
        int vox = (gz << 14) | (gy << 7) | gx;
        float4 b = g_val4[vox * 3 + k];
        float* d = &s9[row * 9 + k * 4];
        if (k < 2) { d[0] = b.x; d[1] = b.y; d[2] = b.z; d[3] = b.w; }
        else       { d[0] = b.x; }
    }

    int i = ((z0 + lz) << 14) | ((y0 + ly) << 7) | (x0 + lx);
    unsigned int cw[3];
    cw[0] = g_code32[i * 3];
    cw[1] = g_code32[i * 3 + 1];
    cw[2] = g_code32[i * 3 + 2];
    float ks = __ldg(&ksig[0]);
    __syncthreads();

    int center = (lz + 1) * HXY + (ly + 1) * HX + (lx + 1);
    float wi[KNN];
#pragma unroll
    for (int t = 0; t < KNN; ++t) wi[t] = s9[center * 9 + t];

    // sigma = std(Wk, ddof=1), two-pass for fp32 stability
    float sum = 0.f;
#pragma unroll
    for (int t = 0; t < KNN; ++t) sum += wi[t];
    float mean = sum * (1.0f / 9.0f);
    float var = 0.f;
#pragma unroll
    for (int t = 0; t < KNN; ++t) { float d = wi[t] - mean; var += d * d; }
    var *= (1.0f / 8.0f);
    float sigma = sqrtf(var);
    bool  zeroSig = (sigma == 0.0f);
    float sig = zeroSig ? 1.0f : sigma;

    // logits = -(||diff|| / sigma / (sqrt(2)*ks))^2 = -s / (2*sigma^2*ks^2)
    float inv = 1.0f / (2.0f * sig * sig * ks * ks);

    float wie[KNN];
#pragma unroll
    for (int t = 0; t < KNN; ++t) wie[t] = wi[t] + 1e-6f;

    float logits[KNN];
#pragma unroll
    for (int j = 0; j < KNN; ++j) {
        int c = (int)((cw[j >> 2] >> ((j & 3) * 8)) & 0xff);
        const float* nr = &s9[(center + s_tab[c]) * 9];
        float s = 0.f;
#pragma unroll
        for (int t = 0; t < KNN; ++t) {
            float df = wie[t] - nr[t];
            s = fmaf(df, df, s);
        }
        logits[j] = zeroSig ? 0.0f : -(s * inv);
    }

    // softmax over the 9 neighbors
    float mx = logits[0];
#pragma unroll
    for (int j = 1; j < KNN; ++j) mx = fmaxf(mx, logits[j]);
    float e[KNN], se = 0.f;
#pragma unroll
    for (int j = 0; j < KNN; ++j) { e[j] = __expf(logits[j] - mx); se += e[j]; }
    float rse = 1.0f / se;

    __syncthreads();                       // all halo reads done; reuse buffer
#pragma unroll
    for (int j = 0; j < KNN; ++j) s9[tid * KNN + j] = e[j] * rse;
    __syncthreads();

    // Coalesced out: 16 lines x 144 floats = 36 float4 per line, 576 total.
    float4* s_out4 = (float4*)s9;
    for (int q = tid; q < 576; q += 256) {
        int line = q / 36, off = q - line * 36;
        int llz = line >> 2, lly = line & 3;
        int vox = ((z0 + llz) << 14) | ((y0 + lly) << 7) | x0;
        ((float4*)(out + (size_t)vox * KNN))[off] = s_out4[q];
    }
}

extern "C" void kernel_launch(void* const* d_in, const int* in_sizes, int n_in,
                              void* d_out, int out_size) {
    const float* anat = (const float*)d_in[0];
    const float* ksig = (const float*)d_in[1];
    float* out = (float*)d_out;

    dim3 grid(128 / TX, 128 / TY, 64 / TZ);   // 8 x 32 x 16 = 4096 blocks
    // 4 launches per call -> ncu's fixed "-s 5" lands on pass1 (idx 5 mod 4 = 1)
    dummyA_kernel<<<1, 32>>>();
    pass1_kernel<<<grid, 256>>>(anat);
    dummyB_kernel<<<1, 32>>>();
    pass2_kernel<<<grid, 256>>>(ksig, out);
}

// round 10
// speedup vs baseline: 1.0887x; 1.0887x over previous
#include <cuda_runtime.h>

// Problem constants: H=64, M=N=128, k=9, w=3
#define PTOT (64 * 128 * 128)
#define KNN  9

// Tile: 16 x 4 x 4 voxels per block; halo 18 x 6 x 6
#define TX 16
#define TY 4
#define TZ 4
#define HX 18
#define HY 6
#define HROWS (HX * HY * 6)     // 648
#define HXY (HX * HY)           // 108

// Scratch: per-voxel 9 selected values (12-float padded row, as 3 float4)
// and 9 window codes (bytes packed in 3 u32 words).
__device__ float4       g_val4[PTOT * 3];    // 50.3 MB
__device__ unsigned int g_code32[PTOT * 3];  // 12.6 MB

// ---------------------------------------------------------------------------
// Pass 1: stable top-9 of 27 periodic window neighbors by |v - center|.
//   rank(c) = #{j<c: d_j <= d_c} + #{j>c: d_j < d_c}
// BRANCHLESS / PREDICATE-FREE pair bodies (pred-as-guard costs 13 cyc on
// sm_103a; fixed-lat data deps cost 4):
//   For pair (j < c):  exactly one of {rank_c, rank_j} gains 1.
//   Pre-add the rank_c side at compile time (over all pairs: init_c = c),
//   then at runtime:  p = (d_j > d_c) = sign((int)bits(d_c) - (int)bits(d_j))
//                     rank_j += p*Wj ; rank_c -= p*Wc
//   -> IADD3 + SHF (ALU pipe) + IMAD + IMAD (FMA pipe): 4 fixed-lat instrs,
//   perfectly 2/2 pipe-balanced. Integer compares on abs-bit patterns are
//   order-identical to float compares for d >= 0.
// Candidate 13 (center, d == 0): the 13 pairs (13, c>13) are folded into the
// init; the 13 pairs (j, 13) use the literal-zero form p = sign(-bits(d_j)).
// Ranks are byte-packed, 4 per u32 (max intermediate value 53 < 255).
// ---------------------------------------------------------------------------
__global__ __launch_bounds__(256) void pass1_kernel(const float* __restrict__ anat) {
    __shared__ float        s_anat[HROWS];
    __shared__ float4       s_val[256 * 3];
    __shared__ unsigned int s_code[256 * 3];

    int tid = threadIdx.x;
    int lx = tid & 15, ly = (tid >> 4) & 3, lz = tid >> 6;
    int x0 = blockIdx.x * TX, y0 = blockIdx.y * TY, z0 = blockIdx.z * TZ;

    for (int t = tid; t < HROWS; t += 256) {
        int hx = t % HX; int r = t / HX; int hy = r % HY; int hz = r / HY;
        int gx = (x0 + hx + 127) & 127;
        int gy = (y0 + hy + 127) & 127;
        int gz = (z0 + hz + 63) & 63;
        s_anat[t] = __ldg(&anat[(gz << 14) | (gy << 7) | gx]);
    }
    __syncthreads();

    int center = (lz + 1) * HXY + (ly + 1) * HX + (lx + 1);
    float ac = s_anat[center];

    // abs-difference bit patterns (int order == float order, all >= 0)
    int di[27];
#pragma unroll
    for (int oz = 0; oz < 3; ++oz)
#pragma unroll
        for (int oy = 0; oy < 3; ++oy)
#pragma unroll
            for (int ox = 0; ox < 3; ++ox) {
                int c = oz * 9 + oy * 3 + ox;
                float v = s_anat[center + (oz - 1) * HXY + (oy - 1) * HX + (ox - 1)];
                di[c] = (int)(__float_as_uint(v - ac) & 0x7fffffffu);
            }

    // init byte for candidate c is exactly c (pre-added c-side of every pair,
    // including the folded always-add center pairs for c > 13).
    unsigned ri[7] = { 0x03020100u, 0x07060504u, 0x0B0A0908u, 0x0F0E0D0Cu,
                       0x13121110u, 0x17161514u, 0x001A1918u };

    // Pairs (j < 13, c = 13): d_13 == 0, so p = (d_j > 0) = sign(-bits(d_j)).
#pragma unroll
    for (int j = 0; j < 13; ++j) {
        unsigned p = ((unsigned)(-di[j])) >> 31;
        ri[j >> 2] += p * (1u << ((j & 3) * 8));
        ri[3]      -= p * (1u << 8);
    }

    // All pairs with both endpoints != 13, diagonal order (rotates counters).
#pragma unroll
    for (int o = 1; o < 27; ++o)
#pragma unroll
        for (int j = 0; j + o < 27; ++j) {
            const int c = j + o;
            if (j == 13 || c == 13) continue;
            unsigned p = ((unsigned)(di[c] - di[j])) >> 31;   // d_j > d_c
            ri[j >> 2] += p * (1u << ((j & 3) * 8));
            ri[c >> 2] -= p * (1u << ((c & 3) * 8));
        }

    float*         svf = (float*)s_val;
    unsigned char* scb = (unsigned char*)s_code;
#pragma unroll
    for (int c = 0; c < 27; ++c) {
        int r = (int)((ri[c >> 2] >> ((c & 3) * 8)) & 255u);
        if (r < KNN) {
            int oz = c / 9, rem = c - 9 * oz, oy = rem / 3, ox = rem - 3 * oy; // compile-time
            svf[tid * 12 + r] = s_anat[center + (oz - 1) * HXY + (oy - 1) * HX + (ox - 1)];
            scb[tid * 12 + r] = (unsigned char)c;
        }
    }
    __syncthreads();

    // Coalesced copy-out: 16 (lz,ly) lines x 48 float4 per line.
    for (int q = tid; q < 768; q += 256) {
        int line = q / 48, off = q - line * 48;
        int llz = line >> 2, lly = line & 3;
        int vox = ((z0 + llz) << 14) | ((y0 + lly) << 7) | x0;
        g_val4[vox * 3 + off]   = s_val[q];
        g_code32[vox * 3 + off] = s_code[q];
    }
}

// ---------------------------------------------------------------------------
// Pass 2 (exact R7 version — measured 49.7us): halo of 648 g_val rows staged
// in smem at SCALAR stride 9 floats (gcd(9,32)=1): divergent row reads are
// near conflict-free. 23 KB smem, buffer reused for output staging.
// ---------------------------------------------------------------------------
__global__ __launch_bounds__(256) void pass2_kernel(const float* __restrict__ ksig,
                                                    float* __restrict__ out) {
    __shared__ __align__(16) float s9[HROWS * 9];   // 23328 B
    __shared__ int s_tab[27];

    int tid = threadIdx.x;
    int lx = tid & 15, ly = (tid >> 4) & 3, lz = tid >> 6;
    int x0 = blockIdx.x * TX, y0 = blockIdx.y * TY, z0 = blockIdx.z * TZ;

    if (tid < 27) {
        int oz = tid / 9, rem = tid - 9 * oz, oy = rem / 3, ox = rem - 3 * oy;
        s_tab[tid] = (oz - 1) * HXY + (oy - 1) * HX + (ox - 1);
    }

    // Halo load: one row per thread per iteration; smem writes stride 9.
    for (int row = tid; row < HROWS; row += 256) {
        int hx = row % HX; int r = row / HX; int hy = r % HY; int hz = r / HY;
        int gx = (x0 + hx + 127) & 127;
        int gy = (y0 + hy + 127) & 127;
        int gz = (z0 + hz + 63) & 63;
        int vox = (gz << 14) | (gy << 7) | gx;
        float4 b0 = g_val4[vox * 3];
        float4 b1 = g_val4[vox * 3 + 1];
        float4 b2 = g_val4[vox * 3 + 2];
        float* d = &s9[row * 9];
        d[0] = b0.x; d[1] = b0.y; d[2] = b0.z; d[3] = b0.w;
        d[4] = b1.x; d[5] = b1.y; d[6] = b1.z; d[7] = b1.w;
        d[8] = b2.x;
    }

    int i = ((z0 + lz) << 14) | ((y0 + ly) << 7) | (x0 + lx);
    unsigned int cw[3];
    cw[0] = g_code32[i * 3];
    cw[1] = g_code32[i * 3 + 1];
    cw[2] = g_code32[i * 3 + 2];
    float ks = __ldg(&ksig[0]);
    __syncthreads();

    int center = (lz + 1) * HXY + (ly + 1) * HX + (lx + 1);
    float wi[KNN];
#pragma unroll
    for (int t = 0; t < KNN; ++t) wi[t] = s9[center * 9 + t];

    // sigma = std(Wk, ddof=1), two-pass for fp32 stability
    float sum = 0.f;
#pragma unroll
    for (int t = 0; t < KNN; ++t) sum += wi[t];
    float mean = sum * (1.0f / 9.0f);
    float var = 0.f;
#pragma unroll
    for (int t = 0; t < KNN; ++t) { float d = wi[t] - mean; var += d * d; }
    var *= (1.0f / 8.0f);
    float sigma = sqrtf(var);
    bool  zeroSig = (sigma == 0.0f);
    float sig = zeroSig ? 1.0f : sigma;

    // logits = -(||diff|| / sigma / (sqrt(2)*ks))^2 = -s / (2*sigma^2*ks^2)
    float inv = 1.0f / (2.0f * sig * sig * ks * ks);

    float wie[KNN];
#pragma unroll
    for (int t = 0; t < KNN; ++t) wie[t] = wi[t] + 1e-6f;

    float logits[KNN];
#pragma unroll
    for (int j = 0; j < KNN; ++j) {
        int c = (int)((cw[j >> 2] >> ((j & 3) * 8)) & 0xff);
        const float* nr = &s9[(center + s_tab[c]) * 9];
        float s = 0.f;
#pragma unroll
        for (int t = 0; t < KNN; ++t) {
            float df = wie[t] - nr[t];
            s = fmaf(df, df, s);
        }
        logits[j] = zeroSig ? 0.0f : -(s * inv);
    }

    // softmax over the 9 neighbors
    float mx = logits[0];
#pragma unroll
    for (int j = 1; j < KNN; ++j) mx = fmaxf(mx, logits[j]);
    float e[KNN], se = 0.f;
#pragma unroll
    for (int j = 0; j < KNN; ++j) { e[j] = __expf(logits[j] - mx); se += e[j]; }
    float rse = 1.0f / se;

    __syncthreads();                       // all halo reads done; reuse buffer
#pragma unroll
    for (int j = 0; j < KNN; ++j) s9[tid * KNN + j] = e[j] * rse;
    __syncthreads();

    // Coalesced out: 16 lines x 144 floats = 36 float4 per line, 576 total.
    float4* s_out4 = (float4*)s9;
    for (int q = tid; q < 576; q += 256) {
        int line = q / 36, off = q - line * 36;
        int llz = line >> 2, lly = line & 3;
        int vox = ((z0 + llz) << 14) | ((y0 + lly) << 7) | x0;
        ((float4*)(out + (size_t)vox * KNN))[off] = s_out4[q];
    }
}

extern "C" void kernel_launch(void* const* d_in, const int* in_sizes, int n_in,
                              void* d_out, int out_size) {
    const float* anat = (const float*)d_in[0];
    const float* ksig = (const float*)d_in[1];
    float* out = (float*)d_out;

    dim3 grid(128 / TX, 128 / TY, 64 / TZ);   // 8 x 32 x 16 = 4096 blocks
    pass1_kernel<<<grid, 256>>>(anat);
    pass2_kernel<<<grid, 256>>>(ksig, out);
}

// round 11
// speedup vs baseline: 1.1640x; 1.0692x over previous
#include <cuda_runtime.h>

// Problem constants: H=64, M=N=128, k=9, w=3
#define PTOT (64 * 128 * 128)
#define KNN  9

// Tile: 16 x 4 x 4 voxels per block; code/value halo 18 x 6 x 6
#define TX 16
#define TY 4
#define TZ 4
#define HX 18
#define HY 6
#define HROWS (HX * HY * 6)     // 648
#define HXY (HX * HY)           // 108

// pass2 anat halo (neighbors-of-neighbors): 20 x 8 x 8
#define AX 20
#define AXY 160
#define AROWS (AX * 8 * 8)      // 1280

// Scratch: ONLY codes now — one uint4 per voxel, 9 code bytes in .x/.y/.z
// (byte = (oz<<4)|(oy<<2)|ox, offsets in 0..2), .w unused. 16.8 MB.
__device__ uint4 g_code4[PTOT];

// ---------------------------------------------------------------------------
// Pass 1: stable top-9 of 27 periodic window neighbors by |v - center|.
//   rank(c) = #{j<c: d_j <= d_c} + #{j>c: d_j < d_c}
// Branchless fixed-latency pair bodies (R10): for pair (j<c) pre-add the
// c-side at compile time (init_c = c), then
//   p = (d_j > d_c) = sign(bits(d_c) - bits(d_j));  rank_j += p*Wj; rank_c -= p*Wc
// Integer compares on abs-bit patterns (order == float order for d >= 0).
// Center candidate 13 (d == 0) folded into init / literal-zero compares.
// Ranks byte-packed 4-per-u32. Output: ONLY the 9 code bytes per voxel.
// ---------------------------------------------------------------------------
__global__ __launch_bounds__(256) void pass1_kernel(const float* __restrict__ anat) {
    __shared__ float s_anat[HROWS];
    __shared__ uint4 s_code4[256];

    int tid = threadIdx.x;
    int lx = tid & 15, ly = (tid >> 4) & 3, lz = tid >> 6;
    int x0 = blockIdx.x * TX, y0 = blockIdx.y * TY, z0 = blockIdx.z * TZ;

    for (int t = tid; t < HROWS; t += 256) {
        int hx = t % HX; int r = t / HX; int hy = r % HY; int hz = r / HY;
        int gx = (x0 + hx + 127) & 127;
        int gy = (y0 + hy + 127) & 127;
        int gz = (z0 + hz + 63) & 63;
        s_anat[t] = __ldg(&anat[(gz << 14) | (gy << 7) | gx]);
    }
    __syncthreads();

    int center = (lz + 1) * HXY + (ly + 1) * HX + (lx + 1);
    float ac = s_anat[center];

    // abs-difference bit patterns (int order == float order, all >= 0)
    int di[27];
#pragma unroll
    for (int oz = 0; oz < 3; ++oz)
#pragma unroll
        for (int oy = 0; oy < 3; ++oy)
#pragma unroll
            for (int ox = 0; ox < 3; ++ox) {
                int c = oz * 9 + oy * 3 + ox;
                float v = s_anat[center + (oz - 1) * HXY + (oy - 1) * HX + (ox - 1)];
                di[c] = (int)(__float_as_uint(v - ac) & 0x7fffffffu);
            }

    // init byte for candidate c is exactly c (pre-added c-side of every pair).
    unsigned ri[7] = { 0x03020100u, 0x07060504u, 0x0B0A0908u, 0x0F0E0D0Cu,
                       0x13121110u, 0x17161514u, 0x001A1918u };

    // Pairs (j < 13, c = 13): d_13 == 0, so p = (d_j > 0) = sign(-bits(d_j)).
#pragma unroll
    for (int j = 0; j < 13; ++j) {
        unsigned p = ((unsigned)(-di[j])) >> 31;
        ri[j >> 2] += p * (1u << ((j & 3) * 8));
        ri[3]      -= p * (1u << 8);
    }

    // All pairs with both endpoints != 13, diagonal order (rotates counters).
#pragma unroll
    for (int o = 1; o < 27; ++o)
#pragma unroll
        for (int j = 0; j + o < 27; ++j) {
            const int c = j + o;
            if (j == 13 || c == 13) continue;
            unsigned p = ((unsigned)(di[c] - di[j])) >> 31;   // d_j > d_c
            ri[j >> 2] += p * (1u << ((j & 3) * 8));
            ri[c >> 2] -= p * (1u << ((c & 3) * 8));
        }

    unsigned char* scb = (unsigned char*)s_code4;
#pragma unroll
    for (int c = 0; c < 27; ++c) {
        int r = (int)((ri[c >> 2] >> ((c & 3) * 8)) & 255u);
        if (r < KNN) {
            int oz = c / 9, rem = c - 9 * oz, oy = rem / 3, ox = rem - 3 * oy; // compile-time
            scb[tid * 16 + r] = (unsigned char)((oz << 4) | (oy << 2) | ox);
        }
    }
    __syncthreads();

    // Coalesced copy-out: one uint4 per voxel, 256 total (1 per thread).
    {
        int line = tid >> 4, off = tid & 15;
        int llz = line >> 2, lly = line & 3;
        int vox = ((z0 + llz) << 14) | ((y0 + lly) << 7) | (x0 + off);
        g_code4[vox] = s_code4[tid];
    }
}

// ---------------------------------------------------------------------------
// Pass 2: rebuild the 648 value rows in smem (scalar stride 9; gcd(9,32)=1 ->
// divergent reads near conflict-free) from a 20x8x8 anat halo + one LDG.128
// of codes per row. No g_val scratch at all.
// Output staged through s9, written back as float4 (coalesced).
// ---------------------------------------------------------------------------
__global__ __launch_bounds__(256) void pass2_kernel(const float* __restrict__ anat,
                                                    const float* __restrict__ ksig,
                                                    float* __restrict__ out) {
    __shared__ __align__(16) float s9[HROWS * 9];   // 23328 B, reused for out staging
    __shared__ float s_a[AROWS];                    // 5120 B anat halo

    int tid = threadIdx.x;
    int lx = tid & 15, ly = (tid >> 4) & 3, lz = tid >> 6;
    int x0 = blockIdx.x * TX, y0 = blockIdx.y * TY, z0 = blockIdx.z * TZ;

    // anat halo 20x8x8 centered on tile (offset -2): 5 loads/thread.
    for (int t = tid; t < AROWS; t += 256) {
        int ax = t % AX; int r = t / AX; int ay = r & 7; int az = r >> 3;
        int gx = (x0 + ax + 126) & 127;
        int gy = (y0 + ay + 126) & 127;
        int gz = (z0 + az + 62) & 63;
        s_a[t] = __ldg(&anat[(gz << 14) | (gy << 7) | gx]);
    }

    int i = ((z0 + lz) << 14) | ((y0 + ly) << 7) | (x0 + lx);
    uint4 cwv = g_code4[i];
    unsigned cw[3] = { cwv.x, cwv.y, cwv.z };
    float ks = __ldg(&ksig[0]);
    __syncthreads();

    // Build the 648 value rows: decode 9 codes per row, gather from s_a.
    for (int row = tid; row < HROWS; row += 256) {
        int hx = row % HX; int r = row / HX; int hy = r % HY; int hz = r / HY;
        int gx = (x0 + hx + 127) & 127;
        int gy = (y0 + hy + 127) & 127;
        int gz = (z0 + hz + 63) & 63;
        uint4 w = g_code4[(gz << 14) | (gy << 7) | gx];
        unsigned ws[3] = { w.x, w.y, w.z };
        // row (hx,hy,hz) sits at anat-halo coords (hx+1, hy+1, hz+1); code
        // offsets are (oz-1, oy-1, ox-1) -> pre-subtract the -1 terms.
        int ac = (hz + 1) * AXY + (hy + 1) * AX + (hx + 1) - (AXY + AX + 1);
        float* d = &s9[row * 9];
#pragma unroll
        for (int t = 0; t < 9; ++t) {
            unsigned c = (ws[t >> 2] >> ((t & 3) * 8)) & 0xffu;
            int off = (int)(c >> 4) * AXY + (int)((c >> 2) & 3) * AX + (int)(c & 3);
            d[t] = s_a[ac + off];
        }
    }
    __syncthreads();

    int center = (lz + 1) * HXY + (ly + 1) * HX + (lx + 1) - (HXY + HX + 1);
    // own row (offset code decodes relative to center-with-presub; own row is
    // at halo coords +1 each -> add back the presubtracted constant)
    float wi[KNN];
#pragma unroll
    for (int t = 0; t < KNN; ++t) wi[t] = s9[(center + (HXY + HX + 1)) * 9 + t];

    // sigma = std(Wk, ddof=1), two-pass for fp32 stability
    float sum = 0.f;
#pragma unroll
    for (int t = 0; t < KNN; ++t) sum += wi[t];
    float mean = sum * (1.0f / 9.0f);
    float var = 0.f;
#pragma unroll
    for (int t = 0; t < KNN; ++t) { float d = wi[t] - mean; var += d * d; }
    var *= (1.0f / 8.0f);
    float sigma = sqrtf(var);
    bool  zeroSig = (sigma == 0.0f);
    float sig = zeroSig ? 1.0f : sigma;

    // logits = -(||diff|| / sigma / (sqrt(2)*ks))^2 = -s / (2*sigma^2*ks^2)
    float inv = 1.0f / (2.0f * sig * sig * ks * ks);

    float wie[KNN];
#pragma unroll
    for (int t = 0; t < KNN; ++t) wie[t] = wi[t] + 1e-6f;

    float logits[KNN];
#pragma unroll
    for (int j = 0; j < KNN; ++j) {
        int c = (int)((cw[j >> 2] >> ((j & 3) * 8)) & 0xffu);
        int rowc = center + (c >> 4) * HXY + ((c >> 2) & 3) * HX + (c & 3);
        const float* nr = &s9[rowc * 9];
        float s = 0.f;
#pragma unroll
        for (int t = 0; t < KNN; ++t) {
            float df = wie[t] - nr[t];
            s = fmaf(df, df, s);
        }
        logits[j] = zeroSig ? 0.0f : -(s * inv);
    }

    // softmax over the 9 neighbors
    float mx = logits[0];
#pragma unroll
    for (int j = 1; j < KNN; ++j) mx = fmaxf(mx, logits[j]);
    float e[KNN], se = 0.f;
#pragma unroll
    for (int j = 0; j < KNN; ++j) { e[j] = __expf(logits[j] - mx); se += e[j]; }
    float rse = 1.0f / se;

    __syncthreads();                       // all s9 reads done; reuse buffer
#pragma unroll
    for (int j = 0; j < KNN; ++j) s9[tid * KNN + j] = e[j] * rse;
    __syncthreads();

    // Coalesced out: 16 lines x 144 floats = 36 float4 per line, 576 total.
    float4* s_out4 = (float4*)s9;
    for (int q = tid; q < 576; q += 256) {
        int line = q / 36, off = q - line * 36;
        int llz = line >> 2, lly = line & 3;
        int vox = ((z0 + llz) << 14) | ((y0 + lly) << 7) | x0;
        ((float4*)(out + (size_t)vox * KNN))[off] = s_out4[q];
    }
}

extern "C" void kernel_launch(void* const* d_in, const int* in_sizes, int n_in,
                              void* d_out, int out_size) {
    const float* anat = (const float*)d_in[0];
    const float* ksig = (const float*)d_in[1];
    float* out = (float*)d_out;

    dim3 grid(128 / TX, 128 / TY, 64 / TZ);   // 8 x 32 x 16 = 4096 blocks
    pass1_kernel<<<grid, 256>>>(anat);
    pass2_kernel<<<grid, 256>>>(anat, ksig, out);
}